// round 3
// baseline (speedup 1.0000x reference)
#include <cuda_runtime.h>
#include <mma.h>
#include <cstdint>
#include <math.h>

using namespace nvcuda;

// Problem constants
#define B_   64
#define S_   2048
#define H_   256
#define H1_  256
#define EPS_ 1e-10f

// ---------------- device scratch (no allocations allowed) ----------------
__device__ float g_decp[B_ * H_];              // 64 KB
__device__ float g_sc2[2 * B_ * S_];           // partial scores per h-half, 1 MB
__device__ float g_ctxpart[16 * B_ * H1_];     // 1 MB

// ---------------- cp.async helpers ----------------
__device__ __forceinline__ uint32_t smem_u32(const void* p) {
    uint32_t a;
    asm("{ .reg .u64 t; cvta.to.shared.u64 t, %1; cvt.u32.u64 %0, t; }"
        : "=r"(a) : "l"(p));
    return a;
}
__device__ __forceinline__ void cp_async16(uint32_t dst, const void* src) {
    asm volatile("cp.async.cg.shared.global [%0], [%1], 16;" :: "r"(dst), "l"(src));
}
#define CP_COMMIT() asm volatile("cp.async.commit_group;" ::: "memory")

// =====================================================================
// Kernel 0: dec_proj[b,h] = sum_k dec[b,k] * W_h[h,k]
// =====================================================================
__global__ void dec_proj_kernel(const float* __restrict__ dec,
                                const float* __restrict__ Wh) {
    int b = blockIdx.x;
    int h = threadIdx.x;
    __shared__ float ds[H_];
    ds[h] = dec[b * H_ + h];
    __syncthreads();
    const float* wr = Wh + (size_t)h * (H_ + H1_);
    float acc = 0.f;
#pragma unroll 8
    for (int k = 0; k < H_; k++) acc = fmaf(ds[k], wr[k], acc);
    g_decp[b * H_ + h] = acc;
}

// =====================================================================
// Kernel 1: scores via WMMA tf32 (mma.sync path, legal on base sm_100)
//
// grid = 64 b * 16 s-tiles * 2 h-halves = 2048 CTAs, 256 threads.
// CTA tile: M=128 (s) x N=128 (h) x K=256, K-chunks of 32, double buffer.
// energy[s,h] = sum_k enc[b,s0+s,k] * Wh[h0+h, 256+k]
// partial_score[s] = sum_{h in half} v[h]*tanh(energy + dec_proj[b,h])
// =====================================================================
#define SK    32           // K chunk (floats)
#define LDA   36           // padded lds (floats) for A/B chunk rows
#define A_F   (128 * LDA)  // floats per A stage
#define STG_F (2 * A_F)    // floats per (A+B) stage
#define EPI_LD 132
#define OFF_VD (2 * STG_F) // float offset of v/dp slices
#define SMEM_F (OFF_VD + 256)
#define SMEM_BYTES (SMEM_F * 4)

__device__ __forceinline__ void load_chunk(int tid, int buf, int ck,
                                           uint32_t sbase,
                                           const float* __restrict__ encb,
                                           const float* __restrict__ Wh,
                                           int h0) {
    uint32_t abase = sbase + (uint32_t)(buf * STG_F) * 4u;
    uint32_t bbase = abase + (uint32_t)A_F * 4u;
    int k0 = ck * SK;
    // A: enc tile 128 rows x 32 floats (row = s_local)
#pragma unroll
    for (int i = 0; i < 4; i++) {
        int idx = tid + 256 * i;
        int row = idx >> 3, g = idx & 7;
        const float* src = encb + (size_t)row * H1_ + k0 + g * 4;
        cp_async16(abase + (uint32_t)(row * LDA + g * 4) * 4u, src);
    }
    // B: W2 tile 128 rows x 32 floats (row = h_local; W2[h,k] = Wh[h, 256+k])
#pragma unroll
    for (int i = 0; i < 4; i++) {
        int idx = tid + 256 * i;
        int row = idx >> 3, g = idx & 7;
        const float* src = Wh + (size_t)(h0 + row) * 512 + 256 + k0 + g * 4;
        cp_async16(bbase + (uint32_t)(row * LDA + g * 4) * 4u, src);
    }
    CP_COMMIT();
}

__global__ void __launch_bounds__(256, 2)
scores_kernel(const float* __restrict__ enc,
              const float* __restrict__ Wh,
              const float* __restrict__ v) {
    extern __shared__ float sm[];
    const int tid  = threadIdx.x;
    const int blk  = blockIdx.x;
    const int hh   = blk & 1;          // h half
    const int st   = (blk >> 1) & 15;  // s tile
    const int b    = blk >> 5;
    const int s0   = st << 7;
    const int h0   = hh << 7;
    uint32_t sbase = smem_u32(sm);
    const float* encb = enc + ((size_t)b * S_ + s0) * H1_;

    // v / dec_proj slices for this h range
    if (tid < 128) sm[OFF_VD + tid]       = v[h0 + tid];
    else           sm[OFF_VD + tid]       = g_decp[b * H_ + h0 + (tid - 128)];

    // warp tiling: 8 warps = 2 (s) x 4 (h); warp tile 64s x 32h
    const int wid = tid >> 5;
    const int ws  = wid & 1;        // 0,1 -> s offset 0/64
    const int wh  = wid >> 1;       // 0..3 -> h offset 0/32/64/96

    wmma::fragment<wmma::accumulator, 16, 16, 8, float> c[4][2];
#pragma unroll
    for (int mi = 0; mi < 4; mi++)
#pragma unroll
        for (int ni = 0; ni < 2; ni++)
            wmma::fill_fragment(c[mi][ni], 0.0f);

    load_chunk(tid, 0, 0, sbase, encb, Wh, h0);
    load_chunk(tid, 1, 1, sbase, encb, Wh, h0);

    for (int ck = 0; ck < 8; ck++) {
        if (ck < 7) asm volatile("cp.async.wait_group 1;" ::: "memory");
        else        asm volatile("cp.async.wait_group 0;" ::: "memory");
        __syncthreads();
        const float* As = sm + (ck & 1) * STG_F;
        const float* Bs = As + A_F;
#pragma unroll
        for (int ks = 0; ks < 4; ks++) {
            wmma::fragment<wmma::matrix_a, 16, 16, 8, wmma::precision::tf32,
                           wmma::row_major> a[4];
            wmma::fragment<wmma::matrix_b, 16, 16, 8, wmma::precision::tf32,
                           wmma::col_major> bf[2];
#pragma unroll
            for (int mi = 0; mi < 4; mi++) {
                wmma::load_matrix_sync(a[mi],
                    As + (ws * 64 + mi * 16) * LDA + ks * 8, LDA);
#pragma unroll
                for (int t = 0; t < a[mi].num_elements; t++)
                    a[mi].x[t] = wmma::__float_to_tf32(a[mi].x[t]);
            }
#pragma unroll
            for (int ni = 0; ni < 2; ni++) {
                wmma::load_matrix_sync(bf[ni],
                    Bs + (wh * 32 + ni * 16) * LDA + ks * 8, LDA);
#pragma unroll
                for (int t = 0; t < bf[ni].num_elements; t++)
                    bf[ni].x[t] = wmma::__float_to_tf32(bf[ni].x[t]);
            }
#pragma unroll
            for (int mi = 0; mi < 4; mi++)
#pragma unroll
                for (int ni = 0; ni < 2; ni++)
                    wmma::mma_sync(c[mi][ni], a[mi], bf[ni], c[mi][ni]);
        }
        __syncthreads();
        if (ck + 2 < 8) load_chunk(tid, ck & 1, ck + 2, sbase, encb, Wh, h0);
    }

    // Epilogue: dump energies to smem (reuse stage buffers), then tanh-dot with v.
    __syncthreads();
#pragma unroll
    for (int mi = 0; mi < 4; mi++)
#pragma unroll
        for (int ni = 0; ni < 2; ni++)
            wmma::store_matrix_sync(
                sm + (ws * 64 + mi * 16) * EPI_LD + wh * 32 + ni * 16,
                c[mi][ni], EPI_LD, wmma::mem_row_major);
    __syncthreads();

    // thread t: row s = t>>1, half = t&1 covers 64 h-cols
    {
        int s = tid >> 1, half = tid & 1;
        const float* er = sm + s * EPI_LD + half * 64;
        const float* vs = sm + OFF_VD + half * 64;
        const float* dp = sm + OFF_VD + 128 + half * 64;
        float acc = 0.f;
#pragma unroll 8
        for (int j = 0; j < 64; j++)
            acc = fmaf(vs[j], tanhf(er[j] + dp[j]), acc);
        // combine the two halves per row via smem
        __syncthreads();
        sm[tid] = acc;           // safe: row s energies already consumed by this thread
        __syncthreads();
        if (tid < 128)
            g_sc2[(hh * B_ + b) * S_ + s0 + tid] = sm[2 * tid] + sm[2 * tid + 1];
    }
}

// =====================================================================
// Kernel 2: masked softmax per batch; writes a into d_out[0 : B*S]
// a_s = e_s*m_s / (sum(e*m) + EPS*sum(e)),  e stabilized by max
// =====================================================================
__global__ void softmax_kernel(const int* __restrict__ mask,
                               float* __restrict__ out_a) {
    int b = blockIdx.x, tid = threadIdx.x;
    __shared__ float red[256];
    float sc[8];
    float mx = -1e30f;
#pragma unroll
    for (int j = 0; j < 8; j++) {
        int s = tid + 256 * j;
        sc[j] = g_sc2[b * S_ + s] + g_sc2[(B_ + b) * S_ + s];
        mx = fmaxf(mx, sc[j]);
    }
    red[tid] = mx; __syncthreads();
    for (int o = 128; o > 0; o >>= 1) {
        if (tid < o) red[tid] = fmaxf(red[tid], red[tid + o]);
        __syncthreads();
    }
    mx = red[0]; __syncthreads();

    float e[8]; int m[8];
    float z = 0.f, smm = 0.f;
#pragma unroll
    for (int j = 0; j < 8; j++) {
        int s = tid + 256 * j;
        e[j] = expf(sc[j] - mx);
        z += e[j];
        m[j] = mask[s * B_ + b];
        smm += m[j] ? e[j] : 0.f;
    }
    red[tid] = z; __syncthreads();
    for (int o = 128; o > 0; o >>= 1) {
        if (tid < o) red[tid] += red[tid + o];
        __syncthreads();
    }
    z = red[0]; __syncthreads();
    red[tid] = smm; __syncthreads();
    for (int o = 128; o > 0; o >>= 1) {
        if (tid < o) red[tid] += red[tid + o];
        __syncthreads();
    }
    smm = red[0];

    float inv = 1.0f / (smm + EPS_ * z);
#pragma unroll
    for (int j = 0; j < 8; j++) {
        int s = tid + 256 * j;
        out_a[b * S_ + s] = m[j] ? e[j] * inv : 0.f;
    }
}

// =====================================================================
// Kernel 3: context partials  ctx_part[sc][b][d] = sum_{i<128} a[b,sc*128+i]*enc[b,sc*128+i,d]
// =====================================================================
__global__ void ctx_part_kernel(const float* __restrict__ enc,
                                const float* __restrict__ a) {
    int sc = blockIdx.x, b = blockIdx.y, d = threadIdx.x;
    __shared__ float as[128];
    if (d < 128) as[d] = a[b * S_ + sc * 128 + d];
    __syncthreads();
    const float* ep = enc + ((size_t)b * S_ + sc * 128) * H1_ + d;
    float acc = 0.f;
#pragma unroll 4
    for (int i = 0; i < 128; i++) acc = fmaf(as[i], ep[(size_t)i * H1_], acc);
    g_ctxpart[(sc * B_ + b) * H1_ + d] = acc;
}

// Kernel 4: reduce 16 partials -> context out
__global__ void ctx_reduce_kernel(float* __restrict__ ctx) {
    int b = blockIdx.x, d = threadIdx.x;
    float acc = 0.f;
#pragma unroll
    for (int sc = 0; sc < 16; sc++) acc += g_ctxpart[(sc * B_ + b) * H1_ + d];
    ctx[b * H1_ + d] = acc;
}

// =====================================================================
extern "C" void kernel_launch(void* const* d_in, const int* in_sizes, int n_in,
                              void* d_out, int out_size) {
    (void)in_sizes; (void)n_in; (void)out_size;
    const float* enc  = (const float*)d_in[0];   // [B,S,H1]
    const float* dec  = (const float*)d_in[1];   // [B,H]
    const int*   mask = (const int*)d_in[2];     // [S,B]
    const float* Wh   = (const float*)d_in[3];   // [H, H+H1]
    const float* v    = (const float*)d_in[4];   // [H]
    float* out = (float*)d_out;                  // a: [B,S] then context: [B,H1]

    static int smem_set = 0;
    if (!smem_set) {
        cudaFuncSetAttribute(scores_kernel,
                             cudaFuncAttributeMaxDynamicSharedMemorySize,
                             SMEM_BYTES);
        smem_set = 1;
    }

    dec_proj_kernel<<<B_, H_>>>(dec, Wh);
    scores_kernel<<<B_ * 16 * 2, 256, SMEM_BYTES>>>(enc, Wh, v);
    softmax_kernel<<<B_, 256>>>(mask, out);
    dim3 g3(16, B_);
    ctx_part_kernel<<<g3, H1_>>>(enc, out);
    ctx_reduce_kernel<<<B_, H1_>>>(out + B_ * S_);
}

// round 6
// speedup vs baseline: 1.0812x; 1.0812x over previous
#include <cuda_runtime.h>
#include <mma.h>
#include <cstdint>
#include <math.h>

using namespace nvcuda;

// Problem constants
#define B_   64
#define S_   2048
#define H_   256
#define H1_  256
#define EPS_ 1e-10f

// ---------------- device scratch (no allocations allowed) ----------------
__device__ float g_decp[B_ * H_];              // 64 KB
__device__ float g_scores[B_ * S_];            // 512 KB
__device__ float g_ctxpart[16 * B_ * H1_];     // 1 MB

// ---------------- cp.async helpers ----------------
__device__ __forceinline__ uint32_t smem_u32(const void* p) {
    uint32_t a;
    asm("{ .reg .u64 t; cvta.to.shared.u64 t, %1; cvt.u32.u64 %0, t; }"
        : "=r"(a) : "l"(p));
    return a;
}
__device__ __forceinline__ void cp_async16(uint32_t dst, const void* src) {
    asm volatile("cp.async.cg.shared.global [%0], [%1], 16;" :: "r"(dst), "l"(src));
}
#define CP_COMMIT() asm volatile("cp.async.commit_group;" ::: "memory")

// fast accurate tanh: (e^{2x}-1)/(e^{2x}+1) via MUFU.EX2 + approx divide (~1e-6 err)
__device__ __forceinline__ float tanh_fast(float x) {
    x = fminf(fmaxf(x, -15.f), 15.f);
    float t = __expf(2.f * x);
    return __fdividef(t - 1.f, t + 1.f);
}

// =====================================================================
// Kernel 0: dec_proj[b,h] = sum_k dec[b,k] * W_h[h,k]
// =====================================================================
__global__ void dec_proj_kernel(const float* __restrict__ dec,
                                const float* __restrict__ Wh) {
    int b = blockIdx.x;
    int h = threadIdx.x;
    __shared__ float ds[H_];
    ds[h] = dec[b * H_ + h];
    __syncthreads();
    const float* wr = Wh + (size_t)h * (H_ + H1_);
    float acc = 0.f;
#pragma unroll 8
    for (int k = 0; k < H_; k++) acc = fmaf(ds[k], wr[k], acc);
    g_decp[b * H_ + h] = acc;
}

// =====================================================================
// Kernel 1: scores via WMMA tf32 (truncated inputs, no cvt)
//
// grid = 64 b * 16 s-tiles = 1024 CTAs, 256 threads.
// CTA tile: M=128 (s) x N=256 (full h) x K=256, K-chunks of 32, double buffer.
// 8 warps as 2(s) x 4(h), warp tile 64x64, c[4][4] accumulators.
// epilogue: energy -> tanh -> dot v -> scores (warp-per-row, shfl reduce)
// =====================================================================
#define SK     32            // K chunk (floats)
#define LDA    36            // padded row stride (floats)
#define A_F    (128 * LDA)   // 4608 floats per A chunk
#define B_F    (256 * LDA)   // 9216 floats per B chunk
#define STG_F  (A_F + B_F)   // 13824 floats per stage
#define EPI_LD 260
#define OFF_VD 33280         // after epilogue region (128*260)
#define SMEM_F (OFF_VD + 512)
#define SMEM_BYTES (SMEM_F * 4)   // 135,168 B

__device__ __forceinline__ void load_chunk(int tid, int buf, int ck,
                                           uint32_t sbase,
                                           const float* __restrict__ encb,
                                           const float* __restrict__ Wh) {
    uint32_t abase = sbase + (uint32_t)(buf * STG_F) * 4u;
    uint32_t bbase = abase + (uint32_t)A_F * 4u;
    int k0 = ck * SK;
    // A: enc tile 128 rows x 32 floats (row = s_local) -> 1024 granules
#pragma unroll
    for (int i = 0; i < 4; i++) {
        int idx = tid + 256 * i;
        int row = idx >> 3, g = idx & 7;
        const float* src = encb + (size_t)row * H1_ + k0 + g * 4;
        cp_async16(abase + (uint32_t)(row * LDA + g * 4) * 4u, src);
    }
    // B: W2 tile 256 rows x 32 floats (row = h; W2[h,k] = Wh[h, 256+k]) -> 2048 granules
#pragma unroll
    for (int i = 0; i < 8; i++) {
        int idx = tid + 256 * i;
        int row = idx >> 3, g = idx & 7;
        const float* src = Wh + (size_t)row * 512 + 256 + k0 + g * 4;
        cp_async16(bbase + (uint32_t)(row * LDA + g * 4) * 4u, src);
    }
    CP_COMMIT();
}

__global__ void __launch_bounds__(256, 1)
scores_kernel(const float* __restrict__ enc,
              const float* __restrict__ Wh,
              const float* __restrict__ v) {
    extern __shared__ float sm[];
    const int tid = threadIdx.x;
    const int st  = blockIdx.x & 15;   // s tile
    const int b   = blockIdx.x >> 4;
    const int s0  = st << 7;
    uint32_t sbase = smem_u32(sm);
    const float* encb = enc + ((size_t)b * S_ + s0) * H1_;

    // v / dec_proj (full 256 each)
    sm[OFF_VD + tid]       = v[tid];
    sm[OFF_VD + 256 + tid] = g_decp[b * H_ + tid];

    // warp tiling: 8 warps = 2 (s) x 4 (h); warp tile 64s x 64h
    const int wid = tid >> 5;
    const int ws  = wid & 1;        // s offset 0/64
    const int wh  = wid >> 1;       // h offset 0/64/128/192

    wmma::fragment<wmma::accumulator, 16, 16, 8, float> c[4][4];
#pragma unroll
    for (int mi = 0; mi < 4; mi++)
#pragma unroll
        for (int ni = 0; ni < 4; ni++)
            wmma::fill_fragment(c[mi][ni], 0.0f);

    load_chunk(tid, 0, 0, sbase, encb, Wh);
    load_chunk(tid, 1, 1, sbase, encb, Wh);

    for (int ck = 0; ck < 8; ck++) {
        if (ck < 7) asm volatile("cp.async.wait_group 1;" ::: "memory");
        else        asm volatile("cp.async.wait_group 0;" ::: "memory");
        __syncthreads();
        const float* As = sm + (ck & 1) * STG_F;
        const float* Bs = As + A_F;
#pragma unroll
        for (int ks = 0; ks < 4; ks++) {
            wmma::fragment<wmma::matrix_a, 16, 16, 8, wmma::precision::tf32,
                           wmma::row_major> a[4];
            wmma::fragment<wmma::matrix_b, 16, 16, 8, wmma::precision::tf32,
                           wmma::col_major> bf[4];
#pragma unroll
            for (int mi = 0; mi < 4; mi++)
                wmma::load_matrix_sync(a[mi],
                    As + (ws * 64 + mi * 16) * LDA + ks * 8, LDA);
#pragma unroll
            for (int ni = 0; ni < 4; ni++)
                wmma::load_matrix_sync(bf[ni],
                    Bs + (wh * 64 + ni * 16) * LDA + ks * 8, LDA);
            // NOTE: no __float_to_tf32 — HMMA.TF32 truncates fp32 mantissa.
#pragma unroll
            for (int mi = 0; mi < 4; mi++)
#pragma unroll
                for (int ni = 0; ni < 4; ni++)
                    wmma::mma_sync(c[mi][ni], a[mi], bf[ni], c[mi][ni]);
        }
        __syncthreads();
        if (ck + 2 < 8) load_chunk(tid, ck & 1, ck + 2, sbase, encb, Wh);
    }

    // Epilogue: dump energies (reuse stage smem), tanh-dot with v, warp-per-row.
    __syncthreads();
#pragma unroll
    for (int mi = 0; mi < 4; mi++)
#pragma unroll
        for (int ni = 0; ni < 4; ni++)
            wmma::store_matrix_sync(
                sm + (ws * 64 + mi * 16) * EPI_LD + wh * 64 + ni * 16,
                c[mi][ni], EPI_LD, wmma::mem_row_major);
    __syncthreads();

    {
        const int lane = tid & 31;
        const float* vs = sm + OFF_VD;
        const float* dp = sm + OFF_VD + 256;
#pragma unroll 1
        for (int i = 0; i < 16; i++) {
            int r = wid * 16 + i;
            const float* er = sm + r * EPI_LD;
            float acc = 0.f;
#pragma unroll
            for (int k = 0; k < 8; k++) {
                int col = lane + 32 * k;
                float e = er[col] + dp[col];
                acc = fmaf(vs[col], tanh_fast(e), acc);
            }
#pragma unroll
            for (int o = 16; o > 0; o >>= 1)
                acc += __shfl_xor_sync(0xffffffffu, acc, o);
            if (lane == 0) g_scores[b * S_ + s0 + r] = acc;
        }
    }
}

// =====================================================================
// Kernel 2: masked softmax per batch; writes a into d_out[0 : B*S]
// a_s = e_s*m_s / (sum(e*m) + EPS*sum(e)),  e stabilized by max
// =====================================================================
__global__ void softmax_kernel(const int* __restrict__ mask,
                               float* __restrict__ out_a) {
    int b = blockIdx.x, tid = threadIdx.x;
    __shared__ float red[256];
    float sc[8];
    float mx = -1e30f;
#pragma unroll
    for (int j = 0; j < 8; j++) {
        sc[j] = g_scores[b * S_ + tid + 256 * j];
        mx = fmaxf(mx, sc[j]);
    }
    red[tid] = mx; __syncthreads();
    for (int o = 128; o > 0; o >>= 1) {
        if (tid < o) red[tid] = fmaxf(red[tid], red[tid + o]);
        __syncthreads();
    }
    mx = red[0]; __syncthreads();

    float e[8]; int m[8];
    float z = 0.f, smm = 0.f;
#pragma unroll
    for (int j = 0; j < 8; j++) {
        int s = tid + 256 * j;
        e[j] = expf(sc[j] - mx);
        z += e[j];
        m[j] = mask[s * B_ + b];
        smm += m[j] ? e[j] : 0.f;
    }
    red[tid] = z; __syncthreads();
    for (int o = 128; o > 0; o >>= 1) {
        if (tid < o) red[tid] += red[tid + o];
        __syncthreads();
    }
    z = red[0]; __syncthreads();
    red[tid] = smm; __syncthreads();
    for (int o = 128; o > 0; o >>= 1) {
        if (tid < o) red[tid] += red[tid + o];
        __syncthreads();
    }
    smm = red[0];

    float inv = 1.0f / (smm + EPS_ * z);
#pragma unroll
    for (int j = 0; j < 8; j++) {
        int s = tid + 256 * j;
        out_a[b * S_ + s] = m[j] ? e[j] * inv : 0.f;
    }
}

// =====================================================================
// Kernel 3: context partials (float4, 4-way row split, high MLP)
// ctx_part[sc][b][:] = sum_{i<128} a[b,sc*128+i]*enc[b,sc*128+i,:]
// =====================================================================
__global__ void ctx_part_kernel(const float* __restrict__ enc,
                                const float* __restrict__ a) {
    int sc = blockIdx.x, b = blockIdx.y, tid = threadIdx.x;
    __shared__ float as[128];
    __shared__ float4 red[256];
    if (tid < 128) as[tid] = a[b * S_ + sc * 128 + tid];
    __syncthreads();
    int c4 = tid & 63;       // float4 column
    int rg = tid >> 6;       // row group 0..3
    const float4* ep = (const float4*)(enc + ((size_t)b * S_ + sc * 128 + rg * 32) * H1_) + c4;
    const float* ar = as + rg * 32;
    float4 acc = make_float4(0.f, 0.f, 0.f, 0.f);
#pragma unroll 8
    for (int i = 0; i < 32; i++) {
        float4 e = ep[(size_t)i * (H1_ / 4)];
        float w = ar[i];
        acc.x = fmaf(w, e.x, acc.x);
        acc.y = fmaf(w, e.y, acc.y);
        acc.z = fmaf(w, e.z, acc.z);
        acc.w = fmaf(w, e.w, acc.w);
    }
    red[tid] = acc;
    __syncthreads();
    if (tid < 64) {
        float4 r0 = red[tid], r1 = red[tid + 64], r2 = red[tid + 128], r3 = red[tid + 192];
        float4 s4;
        s4.x = (r0.x + r1.x) + (r2.x + r3.x);
        s4.y = (r0.y + r1.y) + (r2.y + r3.y);
        s4.z = (r0.z + r1.z) + (r2.z + r3.z);
        s4.w = (r0.w + r1.w) + (r2.w + r3.w);
        ((float4*)(g_ctxpart + (sc * B_ + b) * H1_))[tid] = s4;
    }
}

// Kernel 4: reduce 16 partials -> context out
__global__ void ctx_reduce_kernel(float* __restrict__ ctx) {
    int b = blockIdx.x, d = threadIdx.x;
    float acc = 0.f;
#pragma unroll
    for (int sc = 0; sc < 16; sc++) acc += g_ctxpart[(sc * B_ + b) * H1_ + d];
    ctx[b * H1_ + d] = acc;
}

// =====================================================================
extern "C" void kernel_launch(void* const* d_in, const int* in_sizes, int n_in,
                              void* d_out, int out_size) {
    (void)in_sizes; (void)n_in; (void)out_size;
    const float* enc  = (const float*)d_in[0];   // [B,S,H1]
    const float* dec  = (const float*)d_in[1];   // [B,H]
    const int*   mask = (const int*)d_in[2];     // [S,B]
    const float* Wh   = (const float*)d_in[3];   // [H, H+H1]
    const float* v    = (const float*)d_in[4];   // [H]
    float* out = (float*)d_out;                  // a: [B,S] then context: [B,H1]

    static int smem_set = 0;
    if (!smem_set) {
        cudaFuncSetAttribute(scores_kernel,
                             cudaFuncAttributeMaxDynamicSharedMemorySize,
                             SMEM_BYTES);
        smem_set = 1;
    }

    dec_proj_kernel<<<B_, H_>>>(dec, Wh);
    scores_kernel<<<B_ * 16, 256, SMEM_BYTES>>>(enc, Wh, v);
    softmax_kernel<<<B_, 256>>>(mask, out);
    dim3 g3(16, B_);
    ctx_part_kernel<<<g3, 256>>>(enc, out);
    ctx_reduce_kernel<<<B_, H1_>>>(out + B_ * S_);
}

// round 7
// speedup vs baseline: 1.3843x; 1.2803x over previous
#include <cuda_runtime.h>
#include <cstdint>
#include <math.h>

// Problem constants
#define B_   64
#define S_   2048
#define H_   256
#define H1_  256
#define EPS_ 1e-10f

// ---------------- device scratch (no allocations allowed) ----------------
__device__ float g_decp[B_ * H_];              // 64 KB
__device__ float g_scores[B_ * S_];            // 512 KB

// ---------------- helpers ----------------
__device__ __forceinline__ uint32_t smem_u32(const void* p) {
    uint32_t a;
    asm("{ .reg .u64 t; cvta.to.shared.u64 t, %1; cvt.u32.u64 %0, t; }"
        : "=r"(a) : "l"(p));
    return a;
}
__device__ __forceinline__ void cp_async16(uint32_t dst, const void* src) {
    asm volatile("cp.async.cg.shared.global [%0], [%1], 16;" :: "r"(dst), "l"(src));
}
#define CP_COMMIT() asm volatile("cp.async.commit_group;" ::: "memory")

// fast accurate tanh: (e^{2x}-1)/(e^{2x}+1) via MUFU.EX2 + approx divide (~1e-6 err)
__device__ __forceinline__ float tanh_fast(float x) {
    x = fminf(fmaxf(x, -15.f), 15.f);
    float t = __expf(2.f * x);
    return __fdividef(t - 1.f, t + 1.f);
}

// mma.m16n8k8 tf32 (raw fp32 bits; HW truncates mantissa — validated 4e-4)
__device__ __forceinline__ void mma8(float* c, const uint32_t* a,
                                     uint32_t b0, uint32_t b1) {
    asm volatile(
        "mma.sync.aligned.m16n8k8.row.col.f32.tf32.tf32.f32 "
        "{%0,%1,%2,%3}, {%4,%5,%6,%7}, {%8,%9}, {%0,%1,%2,%3};"
        : "+f"(c[0]), "+f"(c[1]), "+f"(c[2]), "+f"(c[3])
        : "r"(a[0]), "r"(a[1]), "r"(a[2]), "r"(a[3]), "r"(b0), "r"(b1));
}

// =====================================================================
// Kernel 0: dec_proj[b,h] = sum_k dec[b,k] * W_h[h,k]
// =====================================================================
__global__ void dec_proj_kernel(const float* __restrict__ dec,
                                const float* __restrict__ Wh) {
    int b = blockIdx.x;
    int h = threadIdx.x;
    __shared__ float ds[H_];
    ds[h] = dec[b * H_ + h];
    __syncthreads();
    const float* wr = Wh + (size_t)h * (H_ + H1_);
    float acc = 0.f;
#pragma unroll 8
    for (int k = 0; k < H_; k++) acc = fmaf(ds[k], wr[k], acc);
    g_decp[b * H_ + h] = acc;
}

// =====================================================================
// Kernel 1: scores via hand-coded mma.m16n8k8 tf32
//
// grid = 64 b * 16 s-tiles = 1024 CTAs, 256 threads.
// CTA tile M=128(s) x N=256(h) x K=256. 8 warps = 2(s) x 4(h), warp 64x64.
//
// Register-plane smem layout: for each fragment register, its 32 lane
// values occupy one contiguous 128B plane -> LDS.32 at plane+lane*4,
// conflict-free by construction. cp.async 16B granules map 1:1 onto
// plane rows (granule (row,k0..k3) == lanes 4r..4r+3 of one register).
//
// A chunk (128 x 32 floats = 16KB):
//   off_f(row,g) = (row>>4)*512 + (g>>1)*128 + (g&1)*64 + ((row>>3)&1)*32 + (row&7)*4
// B chunk (256 x 32 floats = 32KB):
//   off_f(n,g)   = (n>>3)*256 + (g>>1)*64 + (g&1)*32 + (n&7)*4
// =====================================================================
#define STG_B   49152u             // A 16KB + B 32KB per stage
#define OFF_VD  24576              // float idx: v[256] + dp[256] after 2 stages
#define OFF_RED 25088              // float idx: 128 x 4 reduce
#define SMEM_SC (25600 * 4)        // 102,400 B

__device__ __forceinline__ void load_chunk_sc(int tid, int buf, int ck,
                                              uint32_t sbase,
                                              const float* __restrict__ encb,
                                              const float* __restrict__ Wh) {
    uint32_t ab = sbase + (buf ? STG_B : 0u);
    uint32_t bb = ab + 16384u;
    int k0 = ck * 32;
    int e = tid & 7, gq = (tid >> 3) & 7, rb = tid >> 6;
    uint32_t gof = (uint32_t)((gq >> 1) * 512 + (gq & 1) * 256);
    uint32_t gofB = (uint32_t)((gq >> 1) * 256 + (gq & 1) * 128);
    // A: enc granules (row, k0+4g .. k0+4g+3)
#pragma unroll
    for (int i = 0; i < 4; i++) {
        int row = e + 8 * rb + 32 * i;
        uint32_t off = (uint32_t)((row >> 4) * 2048) + gof
                     + (uint32_t)(((row >> 3) & 1) * 128 + (row & 7) * 16);
        cp_async16(ab + off, encb + (size_t)row * H1_ + k0 + gq * 4);
    }
    // B: W2 granules (n, k0+4g .. k0+4g+3), W2[n][k] = Wh[n][256+k]
#pragma unroll
    for (int i = 0; i < 8; i++) {
        int n = e + 8 * rb + 32 * i;
        uint32_t off = (uint32_t)((n >> 3) * 1024) + gofB
                     + (uint32_t)((n & 7) * 16);
        cp_async16(bb + off, Wh + (size_t)n * 512 + 256 + k0 + gq * 4);
    }
    CP_COMMIT();
}

__global__ void __launch_bounds__(256, 1)
scores_kernel(const float* __restrict__ enc,
              const float* __restrict__ Wh,
              const float* __restrict__ v) {
    extern __shared__ float sm[];
    const int tid = threadIdx.x;
    const int st  = blockIdx.x & 15;
    const int b   = blockIdx.x >> 4;
    const int s0  = st << 7;
    uint32_t sbase = smem_u32(sm);
    const float* encb = enc + ((size_t)b * S_ + s0) * H1_;

    sm[OFF_VD + tid]       = v[tid];
    sm[OFF_VD + 256 + tid] = g_decp[b * H_ + tid];

    const int wid  = tid >> 5, lane = tid & 31;
    const int ws   = wid & 1;        // s half: rows ws*64
    const int wh   = wid >> 1;       // h quarter: cols wh*64

    float c[4][8][4];
#pragma unroll
    for (int t = 0; t < 4; t++)
#pragma unroll
        for (int u = 0; u < 8; u++)
#pragma unroll
            for (int r = 0; r < 4; r++) c[t][u][r] = 0.f;

    load_chunk_sc(tid, 0, 0, sbase, encb, Wh);
    load_chunk_sc(tid, 1, 1, sbase, encb, Wh);

    for (int ck = 0; ck < 8; ck++) {
        if (ck < 7) asm volatile("cp.async.wait_group 1;" ::: "memory");
        else        asm volatile("cp.async.wait_group 0;" ::: "memory");
        __syncthreads();
        const float* As = sm + (ck & 1) * (STG_B / 4);
        const float* Bs = As + 4096;
#pragma unroll
        for (int ks = 0; ks < 4; ks++) {
            uint32_t a[4][4];
#pragma unroll
            for (int t = 0; t < 4; t++) {
                const float* p = As + (ws * 4 + t) * 512 + ks * 128;
                a[t][0] = __float_as_uint(p[lane]);
                a[t][1] = __float_as_uint(p[32 + lane]);
                a[t][2] = __float_as_uint(p[64 + lane]);
                a[t][3] = __float_as_uint(p[96 + lane]);
            }
#pragma unroll
            for (int u = 0; u < 8; u++) {
                const float* q = Bs + (wh * 8 + u) * 256 + ks * 64;
                uint32_t b0 = __float_as_uint(q[lane]);
                uint32_t b1 = __float_as_uint(q[32 + lane]);
#pragma unroll
                for (int t = 0; t < 4; t++)
                    mma8(c[t][u], a[t], b0, b1);
            }
        }
        __syncthreads();
        if (ck + 2 < 8) load_chunk_sc(tid, ck & 1, ck + 2, sbase, encb, Wh);
    }

    // Epilogue from registers: acc c[t][u][2*rh+p] is
    //   row = ws*64 + 16t + (lane>>2) + 8*rh, col = wh*64 + 8u + 2*(lane&3) + p
    const float* vs = sm + OFF_VD;
    const float* dp = sm + OFF_VD + 256;
    float* red = sm + OFF_RED;
#pragma unroll
    for (int t = 0; t < 4; t++)
#pragma unroll
        for (int rh = 0; rh < 2; rh++) {
            float acc = 0.f;
#pragma unroll
            for (int u = 0; u < 8; u++) {
                int hb = wh * 64 + u * 8 + (lane & 3) * 2;
                float e0 = c[t][u][rh * 2]     + dp[hb];
                float e1 = c[t][u][rh * 2 + 1] + dp[hb + 1];
                acc = fmaf(vs[hb],     tanh_fast(e0), acc);
                acc = fmaf(vs[hb + 1], tanh_fast(e1), acc);
            }
            acc += __shfl_xor_sync(0xffffffffu, acc, 1);
            acc += __shfl_xor_sync(0xffffffffu, acc, 2);
            if ((lane & 3) == 0) {
                int row = ws * 64 + t * 16 + (lane >> 2) + rh * 8;
                red[row * 4 + wh] = acc;
            }
        }
    __syncthreads();
    if (tid < 128) {
        float scv = (red[tid * 4] + red[tid * 4 + 1])
                  + (red[tid * 4 + 2] + red[tid * 4 + 3]);
        g_scores[b * S_ + s0 + tid] = scv;
    }
}

// =====================================================================
// Kernel 2: masked softmax per batch; writes a into d_out[0 : B*S]
// a_s = e_s*m_s / (sum(e*m) + EPS*sum(e)),  e stabilized by max
// =====================================================================
__global__ void softmax_kernel(const int* __restrict__ mask,
                               float* __restrict__ out_a) {
    int b = blockIdx.x, tid = threadIdx.x;
    __shared__ float red[256];
    float sc[8];
    float mx = -1e30f;
#pragma unroll
    for (int j = 0; j < 8; j++) {
        sc[j] = g_scores[b * S_ + tid + 256 * j];
        mx = fmaxf(mx, sc[j]);
    }
    red[tid] = mx; __syncthreads();
    for (int o = 128; o > 0; o >>= 1) {
        if (tid < o) red[tid] = fmaxf(red[tid], red[tid + o]);
        __syncthreads();
    }
    mx = red[0]; __syncthreads();

    float e[8]; int m[8];
    float z = 0.f, smm = 0.f;
#pragma unroll
    for (int j = 0; j < 8; j++) {
        int s = tid + 256 * j;
        e[j] = expf(sc[j] - mx);
        z += e[j];
        m[j] = mask[s * B_ + b];
        smm += m[j] ? e[j] : 0.f;
    }
    red[tid] = z; __syncthreads();
    for (int o = 128; o > 0; o >>= 1) {
        if (tid < o) red[tid] += red[tid + o];
        __syncthreads();
    }
    z = red[0]; __syncthreads();
    red[tid] = smm; __syncthreads();
    for (int o = 128; o > 0; o >>= 1) {
        if (tid < o) red[tid] += red[tid + o];
        __syncthreads();
    }
    smm = red[0];

    float inv = 1.0f / (smm + EPS_ * z);
#pragma unroll
    for (int j = 0; j < 8; j++) {
        int s = tid + 256 * j;
        out_a[b * S_ + s] = m[j] ? e[j] * inv : 0.f;
    }
}

// =====================================================================
// Kernel 3: fused context  ctx[b][:] = sum_s a[b,s]*enc[b,s,:]
// grid (B_, 8): CTA handles 32 h-cols for one b, streams all 2048 s.
// =====================================================================
__global__ void __launch_bounds__(256)
ctx_kernel(const float* __restrict__ enc,
           const float* __restrict__ a,
           float* __restrict__ ctx) {
    int b = blockIdx.x, u = blockIdx.y, tid = threadIdx.x;
    __shared__ float as[S_];
    __shared__ float4 red[256];
    for (int i = tid; i < S_; i += 256) as[i] = a[b * S_ + i];
    __syncthreads();
    int c4 = tid & 7;     // float4 slot within 32-col block
    int si = tid >> 3;    // 0..31
    const float4* ep = (const float4*)(enc + (size_t)b * S_ * H1_) + u * 8 + c4;
    float4 acc = make_float4(0.f, 0.f, 0.f, 0.f);
#pragma unroll 4
    for (int s = si; s < S_; s += 32) {
        float4 e = ep[(size_t)s * (H1_ / 4)];
        float w = as[s];
        acc.x = fmaf(w, e.x, acc.x);
        acc.y = fmaf(w, e.y, acc.y);
        acc.z = fmaf(w, e.z, acc.z);
        acc.w = fmaf(w, e.w, acc.w);
    }
    red[tid] = acc;
    __syncthreads();
    for (int o = 128; o >= 8; o >>= 1) {
        if (tid < o) {
            float4 x = red[tid], y = red[tid + o];
            x.x += y.x; x.y += y.y; x.z += y.z; x.w += y.w;
            red[tid] = x;
        }
        __syncthreads();
    }
    if (tid < 8) ((float4*)(ctx + b * H1_ + u * 32))[tid] = red[tid];
}

// =====================================================================
extern "C" void kernel_launch(void* const* d_in, const int* in_sizes, int n_in,
                              void* d_out, int out_size) {
    (void)in_sizes; (void)n_in; (void)out_size;
    const float* enc  = (const float*)d_in[0];   // [B,S,H1]
    const float* dec  = (const float*)d_in[1];   // [B,H]
    const int*   mask = (const int*)d_in[2];     // [S,B]
    const float* Wh   = (const float*)d_in[3];   // [H, H+H1]
    const float* v    = (const float*)d_in[4];   // [H]
    float* out = (float*)d_out;                  // a: [B,S] then context: [B,H1]

    static int smem_set = 0;
    if (!smem_set) {
        cudaFuncSetAttribute(scores_kernel,
                             cudaFuncAttributeMaxDynamicSharedMemorySize,
                             SMEM_SC);
        smem_set = 1;
    }

    dec_proj_kernel<<<B_, H_>>>(dec, Wh);
    scores_kernel<<<B_ * 16, 256, SMEM_SC>>>(enc, Wh, v);
    softmax_kernel<<<B_, 256>>>(mask, out);
    dim3 gc(B_, 8);
    ctx_kernel<<<gc, 256>>>(enc, out, out + B_ * S_);
}